// round 6
// baseline (speedup 1.0000x reference)
#include <cuda_runtime.h>
#include <cuda_bf16.h>
#include <cstdint>

// Problem shape (fixed for this dataset entry)
constexpr int B  = 64;
constexpr int S  = 2048;
constexpr int D  = 512;
constexpr int NM = 1536;   // masked indices per sample
constexpr int NU = 512;    // unmasked indices per sample
constexpr int VEC = D / 4; // 128 float4 per row
constexpr int TOTAL_ROWS = B * (NM + NU); // 131072 row tasks
constexpr float ALPHA = 0.1f;

constexpr int GRID = 148 * 8;   // 1184 blocks

// device-side accumulator + completion ticket (self-resetting across graph replays)
__device__ float        g_acc  = 0.0f;
__device__ unsigned int g_done = 0u;

__device__ __forceinline__ float sq4(const float4& p, const float4& t) {
    float dx = p.x - t.x, dy = p.y - t.y, dz = p.z - t.z, dw = p.w - t.w;
    return dx * dx + dy * dy + dz * dz + dw * dw;
}

__device__ __forceinline__ void row_weight(const int* __restrict__ mask_id,
                                           const int* __restrict__ unmask_id,
                                           int r, float wm, float wu,
                                           int& idx, float& w)
{
    const int b = r >> 11;   // / 2048
    const int j = r & 2047;  // % 2048
    if (j < NM) {
        idx = mask_id[b * NM + j];
        w   = wm;
    } else {
        idx = unmask_id[b * NU + (j - NM)];
        w   = wu;
    }
    idx += b * S;            // fold batch offset into row index
}

__global__ void __launch_bounds__(256)
mae_loss_kernel(const float4* __restrict__ pred,
                const float4* __restrict__ tgt,
                const int* __restrict__ mask_id,
                const int* __restrict__ unmask_id,
                float* __restrict__ out)
{
    const float wm = 1.0f / ((float)B * (float)NM * (float)D);
    const float wu = ALPHA / ((float)B * (float)NU * (float)D);

    const int lane   = threadIdx.x & 31;
    const int warp   = (blockIdx.x * blockDim.x + threadIdx.x) >> 5;
    const int nwarps = (gridDim.x * blockDim.x) >> 5;

    float acc = 0.0f;

    // two rows per warp iteration -> 16 independent LDG.128 in flight
    for (int r = warp; r < TOTAL_ROWS; r += 2 * nwarps) {
        const int r2v = r + nwarps;

        int   idx1, idx2;
        float w1, w2;
        row_weight(mask_id, unmask_id, r, wm, wu, idx1, w1);
        if (r2v < TOTAL_ROWS) {
            row_weight(mask_id, unmask_id, r2v, wm, wu, idx2, w2);
        } else {
            idx2 = idx1;   // safe address, zero weight (branch-free loads)
            w2   = 0.0f;
        }

        const size_t base1 = (size_t)idx1 * (size_t)VEC + lane;
        const size_t base2 = (size_t)idx2 * (size_t)VEC + lane;
        const float4* __restrict__ p1 = pred + base1;
        const float4* __restrict__ t1 = tgt  + base1;
        const float4* __restrict__ p2 = pred + base2;
        const float4* __restrict__ t2 = tgt  + base2;

        // 16 independent LDG.128, front-batched by ptxas
        const float4 a0 = p1[0],  a1 = p1[32], a2 = p1[64], a3 = p1[96];
        const float4 b0 = t1[0],  b1 = t1[32], b2 = t1[64], b3 = t1[96];
        const float4 c0 = p2[0],  c1 = p2[32], c2 = p2[64], c3 = p2[96];
        const float4 d0 = t2[0],  d1 = t2[32], d2 = t2[64], d3 = t2[96];

        acc += w1 * (sq4(a0, b0) + sq4(a1, b1) + sq4(a2, b2) + sq4(a3, b3));
        acc += w2 * (sq4(c0, d0) + sq4(c1, d1) + sq4(c2, d2) + sq4(c3, d3));
    }

    // warp reduce
    #pragma unroll
    for (int off = 16; off > 0; off >>= 1)
        acc += __shfl_xor_sync(0xFFFFFFFFu, acc, off);

    // block reduce across 8 warps
    __shared__ float swarp[8];
    const int wib = threadIdx.x >> 5;
    if (lane == 0) swarp[wib] = acc;
    __syncthreads();

    if (threadIdx.x == 0) {
        float s = 0.0f;
        #pragma unroll
        for (int i = 0; i < 8; i++) s += swarp[i];
        atomicAdd(&g_acc, s);

        // last block publishes the result and resets state for the next replay
        __threadfence();
        unsigned int ticket = atomicAdd(&g_done, 1u);
        if (ticket == (unsigned int)(GRID - 1)) {
            *out  = g_acc;
            g_acc = 0.0f;
            g_done = 0u;
        }
    }
}

extern "C" void kernel_launch(void* const* d_in, const int* in_sizes, int n_in,
                              void* d_out, int out_size)
{
    const float4* pred      = (const float4*)d_in[0];
    const float4* tgt       = (const float4*)d_in[1];
    const int*    mask_id   = (const int*)d_in[2];
    const int*    unmask_id = (const int*)d_in[3];
    float*        out       = (float*)d_out;

    mae_loss_kernel<<<GRID, 256>>>(pred, tgt, mask_id, unmask_id, out);
}

// round 7
// speedup vs baseline: 1.1416x; 1.1416x over previous
#include <cuda_runtime.h>
#include <cuda_bf16.h>
#include <cstdint>

// Problem shape (fixed for this dataset entry)
constexpr int B  = 64;
constexpr int S  = 2048;
constexpr int D  = 512;
constexpr int NM = 1536;   // masked indices per sample
constexpr int NU = 512;    // unmasked indices per sample
constexpr int VEC = D / 4; // 128 float4 per row
constexpr int TOTAL_ROWS = B * (NM + NU); // 131072 row tasks
constexpr float ALPHA = 0.1f;

constexpr int BLOCK = 512;        // 4 CTAs/SM * 16 warps = 64 warps/SM
constexpr int GRID  = 148 * 4;    // 592 blocks
constexpr int WPB   = BLOCK / 32; // 16 warps per block

// device-side accumulator + completion ticket (self-resetting across graph replays)
__device__ float        g_acc  = 0.0f;
__device__ unsigned int g_done = 0u;

__device__ __forceinline__ float sq4(const float4& p, const float4& t) {
    float dx = p.x - t.x, dy = p.y - t.y, dz = p.z - t.z, dw = p.w - t.w;
    return dx * dx + dy * dy + dz * dz + dw * dw;
}

__global__ void __launch_bounds__(BLOCK)
mae_loss_kernel(const float4* __restrict__ pred,
                const float4* __restrict__ tgt,
                const int* __restrict__ mask_id,
                const int* __restrict__ unmask_id,
                float* __restrict__ out)
{
    const float wm = 1.0f / ((float)B * (float)NM * (float)D);
    const float wu = ALPHA / ((float)B * (float)NU * (float)D);

    const int lane   = threadIdx.x & 31;
    const int warp   = (blockIdx.x * blockDim.x + threadIdx.x) >> 5;
    const int nwarps = (gridDim.x * blockDim.x) >> 5;

    float acc = 0.0f;

    // one warp per row: 2048B row = 32 lanes * 4 float4 each
    for (int r = warp; r < TOTAL_ROWS; r += nwarps) {
        const int b = r >> 11;   // / 2048
        const int j = r & 2047;  // % 2048

        int idx;
        float w;
        if (j < NM) {
            idx = mask_id[b * NM + j];
            w   = wm;
        } else {
            idx = unmask_id[b * NU + (j - NM)];
            w   = wu;
        }

        const size_t base = ((size_t)b * S + (size_t)idx) * (size_t)VEC + lane;
        const float4* __restrict__ p = pred + base;
        const float4* __restrict__ t = tgt + base;

        // 8 independent LDG.128, front-batched by ptxas
        const float4 p0 = p[0],  p1 = p[32], p2 = p[64], p3 = p[96];
        const float4 t0 = t[0],  t1 = t[32], t2 = t[64], t3 = t[96];

        acc += w * (sq4(p0, t0) + sq4(p1, t1) + sq4(p2, t2) + sq4(p3, t3));
    }

    // warp reduce
    #pragma unroll
    for (int off = 16; off > 0; off >>= 1)
        acc += __shfl_xor_sync(0xFFFFFFFFu, acc, off);

    // block reduce across 16 warps
    __shared__ float swarp[WPB];
    const int wib = threadIdx.x >> 5;
    if (lane == 0) swarp[wib] = acc;
    __syncthreads();

    if (threadIdx.x == 0) {
        float s = 0.0f;
        #pragma unroll
        for (int i = 0; i < WPB; i++) s += swarp[i];
        atomicAdd(&g_acc, s);

        // last block publishes the result and resets state for the next replay
        __threadfence();
        unsigned int ticket = atomicAdd(&g_done, 1u);
        if (ticket == (unsigned int)(GRID - 1)) {
            *out  = g_acc;
            g_acc = 0.0f;
            g_done = 0u;
        }
    }
}

extern "C" void kernel_launch(void* const* d_in, const int* in_sizes, int n_in,
                              void* d_out, int out_size)
{
    const float4* pred      = (const float4*)d_in[0];
    const float4* tgt       = (const float4*)d_in[1];
    const int*    mask_id   = (const int*)d_in[2];
    const int*    unmask_id = (const int*)d_in[3];
    float*        out       = (float*)d_out;

    mae_loss_kernel<<<GRID, BLOCK>>>(pred, tgt, mask_id, unmask_id, out);
}